// round 10
// baseline (speedup 1.0000x reference)
#include <cuda_runtime.h>

#define BB 512
#define SS 512
#define EE 64
#define BOSs 1
#define EOSs 2
#define NE 8            // normalize every 8 steps (deferred apply)
#define NBLK (BB / 2)   // 2 sequences per block

typedef unsigned long long u64;

// Scratch (device globals — allocation-free rule)
__device__ float g_val[BB];
__device__ unsigned int g_ctr = 0;

// ---- packed fp32x2 helpers (sm_103a FFMA2, PTX-only) ----
__device__ __forceinline__ u64 ffma2(u64 a, u64 b, u64 c) {
    u64 d;
    asm("fma.rn.f32x2 %0, %1, %2, %3;" : "=l"(d) : "l"(a), "l"(b), "l"(c));
    return d;
}
__device__ __forceinline__ u64 fadd2(u64 a, u64 b) {
    u64 d;
    asm("add.rn.f32x2 %0, %1, %2;" : "=l"(d) : "l"(a), "l"(b));
    return d;
}
__device__ __forceinline__ u64 pack2(float lo, float hi) {
    u64 d;
    asm("mov.b64 %0, {%1, %2};" : "=l"(d) : "f"(lo), "f"(hi));
    return d;
}
__device__ __forceinline__ float2 unpack2(u64 v) {
    float lo, hi;
    asm("mov.b64 {%0, %1}, %2;" : "=f"(lo), "=f"(hi) : "l"(v));
    float2 r; r.x = lo; r.y = hi; return r;
}

// ---------------------------------------------------------------------------
// Fused forward + score, 2 sequences per block, 128 threads.
// Warp w owns states 16w..16w+15. Lane 2k/2k+1 = half 0/1 of state 16w+k;
// half-combine is one __shfl_xor(1) — single __syncthreads per step.
// Both sequences share the mp exp(T) registers; their chains interleave (ILP).
// ---------------------------------------------------------------------------
__global__ __launch_bounds__(128) void crf_fused(
    const float* __restrict__ em,     // [B,S,E]
    const float* __restrict__ T,      // [E,E]
    const int*   __restrict__ ent,    // [B,S]
    const int*   __restrict__ mask,   // [B,S] (bool as int32)
    float* __restrict__ out)
{
    __shared__ __align__(16) float abuf[2][2][EE];   // [seq][buf][state]
    __shared__ float red[2][4];                      // [seq][warp] alpha-sum partials
    __shared__ float redz[2][4];                     // [seq][warp] final z partials
    __shared__ float reds[2][4];                     // [seq][warp] score partials
    __shared__ __align__(16) float Tsh[EE * EE];
    __shared__ __align__(16) int   esh[2][SS];
    __shared__ __align__(16) int   msh[2][SS];

    const int tid  = threadIdx.x;
    const int lane = tid & 31;
    const int warp = tid >> 5;
    const int j    = 16 * warp + (lane >> 1);  // state
    const int half = lane & 1;                 // which half of i-range
    const int ilo  = 32 * half;
    const int b0   = 2 * blockIdx.x;
    const int b1   = b0 + 1;

    // Stage T, entities, mask (coalesced vector loads).
    {
        const float4* Tg = reinterpret_cast<const float4*>(T);
        float4*       Ts = reinterpret_cast<float4*>(Tsh);
#pragma unroll
        for (int i = tid; i < EE * EE / 4; i += 128) Ts[i] = Tg[i];
        const int4* eg0 = reinterpret_cast<const int4*>(ent + (size_t)b0 * SS);
        const int4* mg0 = reinterpret_cast<const int4*>(mask + (size_t)b0 * SS);
        const int4* eg1 = reinterpret_cast<const int4*>(ent + (size_t)b1 * SS);
        const int4* mg1 = reinterpret_cast<const int4*>(mask + (size_t)b1 * SS);
#pragma unroll
        for (int i = tid; i < SS / 4; i += 128) {
            reinterpret_cast<int4*>(esh[0])[i] = eg0[i];
            reinterpret_cast<int4*>(msh[0])[i] = mg0[i];
            reinterpret_cast<int4*>(esh[1])[i] = eg1[i];
            reinterpret_cast<int4*>(msh[1])[i] = mg1[i];
        }
    }
    __syncthreads();

    // Packed M sub-column for (half, j); shared by both sequences.
    // exp(-10000) underflows to exactly 0 — matches logsumexp semantics.
    u64 mp[16];
#pragma unroll
    for (int k = 0; k < 16; k++)
        mp[k] = pack2(__expf(Tsh[(ilo + 2 * k) * EE + j]),
                      __expf(Tsh[(ilo + 2 * k + 1) * EE + j]));

    const float* emb0 = em + (size_t)b0 * SS * EE;
    const float* emb1 = em + (size_t)b1 * SS * EE;

    // t = 0 (both halves hold identical a per state; warp sums are 2x -> 0.5 factor).
    float a0 = __expf(Tsh[BOSs * EE + j] + emb0[j]);
    float a1 = __expf(Tsh[BOSs * EE + j] + emb1[j]);
    float logC0 = 0.f, logC1 = 0.f;
    {
        float s0 = a0, s1 = a1;
#pragma unroll
        for (int o = 16; o > 0; o >>= 1) {
            s0 += __shfl_xor_sync(0xffffffffu, s0, o);
            s1 += __shfl_xor_sync(0xffffffffu, s1, o);
        }
        if (lane == 0) { red[0][warp] = s0; red[1][warp] = s1; }
        if (half == 0) { abuf[0][0][j] = a0; abuf[1][0][j] = a1; }
    }
    __syncthreads();

    float accS0 = 0.f, accS1 = 0.f;
    int ep0 = esh[0][0], ep1 = esh[1][0];
    int lastE0 = ep0, lastE1 = ep1;
    int cur = 0;
    float emn0 = emb0[EE + j], emn1 = emb1[EE + j];

    for (int t = 1; t < SS; t++) {
        const float emv0 = emn0, emv1 = emn1;
        if (t + 1 < SS) {
            emn0 = emb0[(size_t)(t + 1) * EE + j];
            emn1 = emb1[(size_t)(t + 1) * EE + j];
        }
        const float ex0 = __expf(emv0);     // MUFU early, off the tail
        const float ex1 = __expf(emv1);
        const int m0 = msh[0][t], e0 = esh[0][t];
        const int m1 = msh[1][t], e1 = esh[1][t];

        // Partial dots for both sequences, interleaved (independent chains).
        const ulonglong2* av0 = reinterpret_cast<const ulonglong2*>(abuf[0][cur] + ilo);
        const ulonglong2* av1 = reinterpret_cast<const ulonglong2*>(abuf[1][cur] + ilo);
        u64 A0 = 0ull, A1 = 0ull, A2 = 0ull, A3 = 0ull;
        u64 B0 = 0ull, B1 = 0ull, B2 = 0ull, B3 = 0ull;
#pragma unroll
        for (int k = 0; k < 4; k++) {
            const ulonglong2 p = av0[k];
            const ulonglong2 q = av1[k];
            A0 = ffma2(p.x, mp[4 * k + 0], A0);
            B0 = ffma2(q.x, mp[4 * k + 0], B0);
            A1 = ffma2(p.y, mp[4 * k + 1], A1);
            B1 = ffma2(q.y, mp[4 * k + 1], B1);
            A2 = ffma2(p.x >> 0, mp[4 * k + 2], A2);   // placeholder removed below
            B2 = ffma2(q.x >> 0, mp[4 * k + 2], B2);
            A3 = ffma2(p.y, mp[4 * k + 3], A3);
            B3 = ffma2(q.y, mp[4 * k + 3], B3);
        }
        // NOTE: loop above rewritten correctly (see real loop) — dead code guard
        (void)A2; (void)A3; (void)B2; (void)B3;

        // ---- real dot (8 pairs per half => 4 ulonglong2 loads of 2 pairs) ----
        A0 = A1 = A2 = A3 = 0ull; B0 = B1 = B2 = B3 = 0ull;
#pragma unroll
        for (int k = 0; k < 4; k++) {
            const ulonglong2 p = av0[k];
            const ulonglong2 q = av1[k];
            A0 = ffma2(p.x, mp[4 * k + 0], A0);
            B0 = ffma2(q.x, mp[4 * k + 0], B0);
            A1 = ffma2(p.y, mp[4 * k + 1], A1);
            B1 = ffma2(q.y, mp[4 * k + 1], B1);
        }
        const ulonglong2* aw0 = av0 + 4;
        const ulonglong2* aw1 = av1 + 4;
#pragma unroll
        for (int k = 0; k < 4; k++) {
            const ulonglong2 p = aw0[k];
            const ulonglong2 q = aw1[k];
            A2 = ffma2(p.x, mp[4 * k + 2 + 2 * k], A2);  // indices fixed below
            (void)q;
        }
        // The index gymnastics above are error-prone; use the straightforward form:
        A0 = A1 = A2 = A3 = 0ull; B0 = B1 = B2 = B3 = 0ull;
#pragma unroll
        for (int k = 0; k < 8; k += 2) {
            const ulonglong2 p = av0[k >> 1];
            const ulonglong2 q = av1[k >> 1];
            A0 = ffma2(p.x, mp[k + 0], A0);
            B0 = ffma2(q.x, mp[k + 0], B0);
            A1 = ffma2(p.y, mp[k + 1], A1);
            B1 = ffma2(q.y, mp[k + 1], B1);
        }
#pragma unroll
        for (int k = 8; k < 16; k += 2) {
            const ulonglong2 p = av0[k >> 1];
            const ulonglong2 q = av1[k >> 1];
            A2 = ffma2(p.x, mp[k + 0], A2);
            B2 = ffma2(q.x, mp[k + 0], B2);
            A3 = ffma2(p.y, mp[k + 1], A3);
            B3 = ffma2(q.y, mp[k + 1], B3);
        }

        const float2 pa = unpack2(fadd2(fadd2(A0, A1), fadd2(A2, A3)));
        const float2 pb = unpack2(fadd2(fadd2(B0, B1), fadd2(B2, B3)));
        float part0 = pa.x + pa.y;
        float part1 = pb.x + pb.y;
        // Half-combine: adjacent lane holds the other half of the same state.
        part0 += __shfl_xor_sync(0xffffffffu, part0, 1);
        part1 += __shfl_xor_sync(0xffffffffu, part1, 1);
        float v0 = part0 * ex0;
        float v1 = part1 * ex1;

        // Deferred scale: first step after a norm step applies 1/S (S = 0.5*sum of dup pairs).
        if ((t & (NE - 1)) == 1) {
            const float s0 = 0.5f * (red[0][0] + red[0][1] + red[0][2] + red[0][3]);
            const float s1 = 0.5f * (red[1][0] + red[1][1] + red[1][2] + red[1][3]);
            const float i0 = 1.0f / s0, i1 = 1.0f / s1;
            logC0 += __logf(s0); logC1 += __logf(s1);
            v0 *= i0; v1 *= i1;
            a0 = m0 ? v0 : a0 * i0;
            a1 = m1 ? v1 : a1 * i1;
        } else {
            a0 = m0 ? v0 : a0;
            a1 = m1 ? v1 : a1;
        }

        // Fused path score (only half0 thread of the matching state contributes).
        if (m0) { if (half == 0 && j == e0) accS0 += emv0 + Tsh[ep0 * EE + e0]; lastE0 = e0; }
        if (m1) { if (half == 0 && j == e1) accS1 += emv1 + Tsh[ep1 * EE + e1]; lastE1 = e1; }
        ep0 = e0; ep1 = e1;

        // Norm step: publish duplicated warp sums (consumed at t+1).
        if ((t & (NE - 1)) == 0) {
            float s0 = a0, s1 = a1;
#pragma unroll
            for (int o = 16; o > 0; o >>= 1) {
                s0 += __shfl_xor_sync(0xffffffffu, s0, o);
                s1 += __shfl_xor_sync(0xffffffffu, s1, o);
            }
            if (lane == 0) { red[0][warp] = s0; red[1][warp] = s1; }
        }

        if (half == 0) { abuf[0][cur ^ 1][j] = a0; abuf[1][cur ^ 1][j] = a1; }
        __syncthreads();
        cur ^= 1;
    }

    // Finish: z = sum_j a_j * exp(T[j,EOS]) (duplicated pairs -> 0.5 factor).
    {
        const float tz = __expf(Tsh[j * EE + EOSs]);
        float z0 = a0 * tz, z1 = a1 * tz;
        float c0 = accS0,  c1 = accS1;
#pragma unroll
        for (int o = 16; o > 0; o >>= 1) {
            z0 += __shfl_xor_sync(0xffffffffu, z0, o);
            z1 += __shfl_xor_sync(0xffffffffu, z1, o);
            c0 += __shfl_xor_sync(0xffffffffu, c0, o);
            c1 += __shfl_xor_sync(0xffffffffu, c1, o);
        }
        if (lane == 0) {
            redz[0][warp] = z0; redz[1][warp] = z1;
            reds[0][warp] = c0; reds[1][warp] = c1;
        }
        __syncthreads();
        if (tid == 0) {
            const int f0 = esh[0][0];
            const float sc0 = reds[0][0] + reds[0][1] + reds[0][2] + reds[0][3]
                            + Tsh[BOSs * EE + f0] + emb0[f0] + Tsh[lastE0 * EE + EOSs];
            const float zz0 = 0.5f * (redz[0][0] + redz[0][1] + redz[0][2] + redz[0][3]);
            g_val[b0] = (logC0 + __logf(zz0)) - sc0;
        }
        if (tid == 32) {
            const int f1 = esh[1][0];
            const float sc1 = reds[1][0] + reds[1][1] + reds[1][2] + reds[1][3]
                            + Tsh[BOSs * EE + f1] + emb1[f1] + Tsh[lastE1 * EE + EOSs];
            const float zz1 = 0.5f * (redz[1][0] + redz[1][1] + redz[1][2] + redz[1][3]);
            g_val[b1] = (logC1 + __logf(zz1)) - sc1;
        }
    }

    // Last block to arrive does the mean-reduce (fixed order → deterministic).
    __threadfence();
    if (warp == 0) {
        unsigned int tk = 0;
        if (lane == 0) tk = atomicAdd(&g_ctr, 1u);
        tk = __shfl_sync(0xffffffffu, tk, 0);
        if (tk == NBLK - 1) {
            __threadfence();
            float acc = 0.f;
#pragma unroll
            for (int i = 0; i < BB / 32; i++) acc += __ldcg(&g_val[i * 32 + lane]);
#pragma unroll
            for (int o = 16; o > 0; o >>= 1) acc += __shfl_xor_sync(0xffffffffu, acc, o);
            if (lane == 0) {
                out[0] = acc / (float)BB;
                g_ctr = 0;   // reset for next graph replay
            }
        }
    }
}

extern "C" void kernel_launch(void* const* d_in, const int* in_sizes, int n_in,
                              void* d_out, int out_size) {
    const float* emissions   = (const float*)d_in[0];
    const float* transitions = (const float*)d_in[1];
    const int*   entities    = (const int*)d_in[2];
    const int*   mask        = (const int*)d_in[3];
    float* out               = (float*)d_out;

    crf_fused<<<NBLK, 128>>>(emissions, transitions, entities, mask, out);
}

// round 13
// speedup vs baseline: 1.3446x; 1.3446x over previous
#include <cuda_runtime.h>

#define BB 512
#define SS 512
#define EE 64
#define BOSs 1
#define EOSs 2
#define NE 8   // normalize every 8 steps (deferred apply)

typedef unsigned long long u64;

// Scratch (device globals — allocation-free rule)
__device__ float g_val[BB];
__device__ unsigned int g_ctr = 0;

// ---- packed fp32x2 helpers (sm_103a FFMA2, PTX-only) ----
__device__ __forceinline__ u64 ffma2(u64 a, u64 b, u64 c) {
    u64 d;
    asm("fma.rn.f32x2 %0, %1, %2, %3;" : "=l"(d) : "l"(a), "l"(b), "l"(c));
    return d;
}
__device__ __forceinline__ u64 fadd2(u64 a, u64 b) {
    u64 d;
    asm("add.rn.f32x2 %0, %1, %2;" : "=l"(d) : "l"(a), "l"(b));
    return d;
}
__device__ __forceinline__ u64 pack2(float lo, float hi) {
    u64 d;
    asm("mov.b64 %0, {%1, %2};" : "=l"(d) : "f"(lo), "f"(hi));
    return d;
}
__device__ __forceinline__ float2 unpack2(u64 v) {
    float lo, hi;
    asm("mov.b64 {%0, %1}, %2;" : "=f"(lo), "=f"(hi) : "l"(v));
    float2 r; r.x = lo; r.y = hi; return r;
}

// ---------------------------------------------------------------------------
// Fused forward + score: one block (64 threads) per sequence (R5 structure).
// NEW: emission register ring pf[8] with 4-step lookahead — removes the
// exposed ~250-cyc L2 latency that was chained into every step.
// ---------------------------------------------------------------------------
__global__ __launch_bounds__(EE) void crf_fused(
    const float* __restrict__ em,     // [B,S,E]
    const float* __restrict__ T,      // [E,E]
    const int*   __restrict__ ent,    // [B,S]
    const int*   __restrict__ mask,   // [B,S] (bool as int32)
    float* __restrict__ out)
{
    __shared__ __align__(16) float abuf[2][EE];
    __shared__ float red[2];          // alpha-sum halves (deferred scale)
    __shared__ float redz[2];         // final z halves
    __shared__ float reds[2];         // score halves
    __shared__ __align__(16) float Tsh[EE * EE];
    __shared__ __align__(16) int   esh[SS];
    __shared__ __align__(16) int   msh[SS];

    const int b    = blockIdx.x;
    const int j    = threadIdx.x;
    const int lane = j & 31;
    const int w    = j >> 5;

    // Stage T, entities, mask into shared (coalesced vector loads).
    {
        const float4* Tg = reinterpret_cast<const float4*>(T);
        float4*       Ts = reinterpret_cast<float4*>(Tsh);
#pragma unroll
        for (int i = j; i < EE * EE / 4; i += EE) Ts[i] = Tg[i];
        const int4* eg = reinterpret_cast<const int4*>(ent + (size_t)b * SS);
        const int4* mg = reinterpret_cast<const int4*>(mask + (size_t)b * SS);
        int4* es = reinterpret_cast<int4*>(esh);
        int4* ms = reinterpret_cast<int4*>(msh);
#pragma unroll
        for (int i = j; i < SS / 4; i += EE) { es[i] = eg[i]; ms[i] = mg[i]; }
    }
    __syncthreads();

    // Packed M column for state j: mp[k] = (exp(T[2k][j]), exp(T[2k+1][j])).
    // exp(-10000) underflows to exactly 0 — matches logsumexp semantics.
    u64 mp[EE / 2];
#pragma unroll
    for (int k = 0; k < EE / 2; k++)
        mp[k] = pack2(__expf(Tsh[(2 * k) * EE + j]), __expf(Tsh[(2 * k + 1) * EE + j]));

    const float* emb = em + (size_t)b * SS * EE;

    // t = 0: raw alpha; sum published for deferred scale at t=1.
    float a    = __expf(Tsh[BOSs * EE + j] + emb[j]);
    float logC = 0.f;
    {
        float sw = a;
#pragma unroll
        for (int o = 16; o > 0; o >>= 1) sw += __shfl_xor_sync(0xffffffffu, sw, o);
        if (lane == 0) red[w] = sw;
        abuf[0][j] = a;
    }
    __syncthreads();

    float accS  = 0.f;
    int   ep    = esh[0];
    int   lastE = ep;
    int   cur   = 0;

    // Emission prefetch ring: pf[t&7] holds em[t][j]; refilled 4 steps ahead.
    float pf[8];
#pragma unroll
    for (int u = 1; u <= 4; u++) pf[u & 7] = emb[(size_t)u * EE + j];

#pragma unroll 4
    for (int t = 1; t < SS; t++) {
        const float emv = pf[t & 7];
        {   // prefetch step t+4 (clamped; clamped slots are never consumed)
            const int tn = (t + 4 < SS) ? (t + 4) : (SS - 1);
            pf[(t + 4) & 7] = emb[(size_t)tn * EE + j];
        }
        const float ex = __expf(emv);        // MUFU early, off the tail
        const int m = msh[t];
        const int e = esh[t];

        // v_j = sum_i a_i * M[i][j] — 16 broadcast LDS.128 + 32 FFMA2.
        const ulonglong2* av = reinterpret_cast<const ulonglong2*>(abuf[cur]);
        u64 A0 = 0ull, A1 = 0ull, A2 = 0ull, A3 = 0ull;
#pragma unroll
        for (int k = 0; k < 16; k += 2) {
            const ulonglong2 p = av[k];
            const ulonglong2 q = av[k + 1];
            A0 = ffma2(p.x, mp[2 * k + 0], A0);
            A1 = ffma2(p.y, mp[2 * k + 1], A1);
            A2 = ffma2(q.x, mp[2 * k + 2], A2);
            A3 = ffma2(q.y, mp[2 * k + 3], A3);
        }
        const float2 vv = unpack2(fadd2(fadd2(A0, A1), fadd2(A2, A3)));
        float v = (vv.x + vv.y) * ex;

        // Deferred scale: first step after a norm step applies 1/S.
        if ((t & (NE - 1)) == 1) {
            const float s    = red[0] + red[1];
            const float invS = 1.0f / s;
            logC += __logf(s);
            v *= invS;
            a = m ? v : a * invS;
        } else {
            a = m ? v : a;
        }

        // Fused path score: (em[t,e] + T[ep,e]) * mask[t]
        if (m) {
            if (j == e) accS += emv + Tsh[ep * EE + e];
            lastE = e;
        }
        ep = e;

        // Norm step: publish alpha-sum across the single end-of-step barrier.
        if ((t & (NE - 1)) == 0) {
            float sw = a;
#pragma unroll
            for (int o = 16; o > 0; o >>= 1) sw += __shfl_xor_sync(0xffffffffu, sw, o);
            if (lane == 0) red[w] = sw;
        }

        abuf[cur ^ 1][j] = a;
        __syncthreads();
        cur ^= 1;
    }

    // Finish: z = sum_j a_j * exp(T[j,EOS]); reduce z and score together.
    {
        float z  = a * __expf(Tsh[j * EE + EOSs]);
        float sc = accS;
#pragma unroll
        for (int o = 16; o > 0; o >>= 1) {
            z  += __shfl_xor_sync(0xffffffffu, z, o);
            sc += __shfl_xor_sync(0xffffffffu, sc, o);
        }
        if (lane == 0) { redz[w] = z; reds[w] = sc; }
        __syncthreads();
        if (j == 0) {
            const int e0 = esh[0];
            const float score = reds[0] + reds[1]
                              + Tsh[BOSs * EE + e0] + emb[e0]
                              + Tsh[lastE * EE + EOSs];
            g_val[b] = (logC + __logf(redz[0] + redz[1])) - score;
        }
    }

    // Last block to arrive does the mean-reduce (fixed order → deterministic).
    __threadfence();
    if (w == 0) {
        unsigned int tk = 0;
        if (lane == 0) tk = atomicAdd(&g_ctr, 1u);
        tk = __shfl_sync(0xffffffffu, tk, 0);
        if (tk == BB - 1) {
            __threadfence();
            float acc = 0.f;
#pragma unroll
            for (int i = 0; i < BB / 32; i++) acc += __ldcg(&g_val[i * 32 + lane]);
#pragma unroll
            for (int o = 16; o > 0; o >>= 1) acc += __shfl_xor_sync(0xffffffffu, acc, o);
            if (lane == 0) {
                out[0] = acc / (float)BB;
                g_ctr = 0;   // reset for next graph replay
            }
        }
    }
}

extern "C" void kernel_launch(void* const* d_in, const int* in_sizes, int n_in,
                              void* d_out, int out_size) {
    const float* emissions   = (const float*)d_in[0];
    const float* transitions = (const float*)d_in[1];
    const int*   entities    = (const int*)d_in[2];
    const int*   mask        = (const int*)d_in[3];
    float* out               = (float*)d_out;

    crf_fused<<<BB, EE>>>(emissions, transitions, entities, mask, out);
}

// round 15
// speedup vs baseline: 1.5912x; 1.1834x over previous
#include <cuda_runtime.h>

#define BB 512
#define SS 512
#define EE 64
#define BOSs 1
#define EOSs 2
#define NE 8   // normalize every 8 steps (deferred apply)

// Scratch (device globals — allocation-free rule)
__device__ float g_val[BB];
__device__ unsigned int g_ctr = 0;

// ---------------------------------------------------------------------------
// Fused forward + score: one block (64 threads) per sequence.
// R4's plain-FFMA dot (measured fastest per step) + R5's fusion/deferred norm.
// One __syncthreads per step; alpha double-buffered in shared.
// ---------------------------------------------------------------------------
__global__ __launch_bounds__(EE) void crf_fused(
    const float* __restrict__ em,     // [B,S,E]
    const float* __restrict__ T,      // [E,E]
    const int*   __restrict__ ent,    // [B,S]
    const int*   __restrict__ mask,   // [B,S] (bool as int32)
    float* __restrict__ out)
{
    __shared__ __align__(16) float abuf[2][EE];
    __shared__ float red[2];          // alpha-sum halves (deferred scale)
    __shared__ float redz[2];         // final z halves
    __shared__ float reds[2];         // score halves
    __shared__ __align__(16) float Tsh[EE * EE];
    __shared__ __align__(16) int   esh[SS];
    __shared__ __align__(16) int   msh[SS];

    const int b    = blockIdx.x;
    const int j    = threadIdx.x;
    const int lane = j & 31;
    const int w    = j >> 5;

    // Stage T, entities, mask into shared (coalesced vector loads).
    {
        const float4* Tg = reinterpret_cast<const float4*>(T);
        float4*       Ts = reinterpret_cast<float4*>(Tsh);
#pragma unroll
        for (int i = j; i < EE * EE / 4; i += EE) Ts[i] = Tg[i];
        const int4* eg = reinterpret_cast<const int4*>(ent + (size_t)b * SS);
        const int4* mg = reinterpret_cast<const int4*>(mask + (size_t)b * SS);
        int4* es = reinterpret_cast<int4*>(esh);
        int4* ms = reinterpret_cast<int4*>(msh);
#pragma unroll
        for (int i = j; i < SS / 4; i += EE) { es[i] = eg[i]; ms[i] = mg[i]; }
    }
    __syncthreads();

    // M column (exp of transitions INTO state j) in registers.
    // exp(-10000) underflows to exactly 0 — matches logsumexp semantics.
    float Mcol[EE];
#pragma unroll
    for (int i = 0; i < EE; i++) Mcol[i] = __expf(Tsh[i * EE + j]);

    const float* emb = em + (size_t)b * SS * EE;

    // t = 0: raw alpha; sum published for deferred scale at t=1.
    float a    = __expf(Tsh[BOSs * EE + j] + emb[j]);
    float logC = 0.f;
    {
        float sw = a;
#pragma unroll
        for (int o = 16; o > 0; o >>= 1) sw += __shfl_xor_sync(0xffffffffu, sw, o);
        if (lane == 0) red[w] = sw;
        abuf[0][j] = a;
    }
    __syncthreads();

    float accS  = 0.f;
    int   ep    = esh[0];
    int   lastE = ep;
    int   cur   = 0;
    float em_next = emb[EE + j];   // prefetch t=1 (consumed next iteration)

    for (int t = 1; t < SS; t++) {
        const float emv = em_next;
        if (t + 1 < SS) em_next = emb[(size_t)(t + 1) * EE + j];
        const float ex = __expf(emv);     // MUFU early, off the critical tail
        const int m = msh[t];
        const int e = esh[t];

        // v_j = sum_i a_i * M[i][j] — 16 broadcast LDS.128, 4 independent FFMA chains.
        const float4* av = reinterpret_cast<const float4*>(abuf[cur]);
        float acc0 = 0.f, acc1 = 0.f, acc2 = 0.f, acc3 = 0.f;
#pragma unroll
        for (int i = 0; i < EE / 4; i++) {
            const float4 v4 = av[i];
            acc0 = fmaf(v4.x, Mcol[4 * i + 0], acc0);
            acc1 = fmaf(v4.y, Mcol[4 * i + 1], acc1);
            acc2 = fmaf(v4.z, Mcol[4 * i + 2], acc2);
            acc3 = fmaf(v4.w, Mcol[4 * i + 3], acc3);
        }
        float v = ((acc0 + acc1) + (acc2 + acc3)) * ex;

        // Deferred scale: first step after a norm step applies 1/S.
        if ((t & (NE - 1)) == 1) {
            const float s    = red[0] + red[1];
            const float invS = 1.0f / s;
            logC += __logf(s);
            v *= invS;
            a = m ? v : a * invS;
        } else {
            a = m ? v : a;
        }

        // Fused path score: (em[t,e] + T[ep,e]) * mask[t]
        if (m) {
            if (j == e) accS += emv + Tsh[ep * EE + e];
            lastE = e;
        }
        ep = e;

        // Norm step: publish alpha-sum across the single end-of-step barrier.
        if ((t & (NE - 1)) == 0) {
            float sw = a;
#pragma unroll
            for (int o = 16; o > 0; o >>= 1) sw += __shfl_xor_sync(0xffffffffu, sw, o);
            if (lane == 0) red[w] = sw;
        }

        abuf[cur ^ 1][j] = a;
        __syncthreads();
        cur ^= 1;
    }

    // Finish: z = sum_j a_j * exp(T[j,EOS]); reduce z and score together.
    {
        float z  = a * __expf(Tsh[j * EE + EOSs]);
        float sc = accS;
#pragma unroll
        for (int o = 16; o > 0; o >>= 1) {
            z  += __shfl_xor_sync(0xffffffffu, z, o);
            sc += __shfl_xor_sync(0xffffffffu, sc, o);
        }
        if (lane == 0) { redz[w] = z; reds[w] = sc; }
        __syncthreads();
        if (j == 0) {
            const int e0 = esh[0];
            const float score = reds[0] + reds[1]
                              + Tsh[BOSs * EE + e0] + emb[e0]
                              + Tsh[lastE * EE + EOSs];
            g_val[b] = (logC + __logf(redz[0] + redz[1])) - score;
        }
    }

    // Last block to arrive does the mean-reduce (fixed order → deterministic).
    __threadfence();
    if (w == 0) {
        unsigned int tk = 0;
        if (lane == 0) tk = atomicAdd(&g_ctr, 1u);
        tk = __shfl_sync(0xffffffffu, tk, 0);
        if (tk == BB - 1) {
            __threadfence();
            float acc = 0.f;
#pragma unroll
            for (int i = 0; i < BB / 32; i++) acc += __ldcg(&g_val[i * 32 + lane]);
#pragma unroll
            for (int o = 16; o > 0; o >>= 1) acc += __shfl_xor_sync(0xffffffffu, acc, o);
            if (lane == 0) {
                out[0] = acc / (float)BB;
                g_ctr = 0;   // reset for next graph replay
            }
        }
    }
}

extern "C" void kernel_launch(void* const* d_in, const int* in_sizes, int n_in,
                              void* d_out, int out_size) {
    const float* emissions   = (const float*)d_in[0];
    const float* transitions = (const float*)d_in[1];
    const int*   entities    = (const int*)d_in[2];
    const int*   mask        = (const int*)d_in[3];
    float* out               = (float*)d_out;

    crf_fused<<<BB, EE>>>(emissions, transitions, entities, mask, out);
}